// round 14
// baseline (speedup 1.0000x reference)
#include <cuda_runtime.h>
#include <cuda_bf16.h>

#define D 2048
#define B 16

#define NGBLK 256      // gates blocks: 8 cols each, 2 waves -> staggered slices
#define WGRID 2048     // writer blocks: 16 slices x 16 batches x 8 row-chunks

#define XPAD 1028                  // words per staged x row (conflict-free frags)
#define SMEM_WORDS (2 * B * XPAD)  // rbuf aliases staging (dead after mainloop)
#define SMEM_BYTES (SMEM_WORDS * 4)

// Scratch + sync state (allocation-free rule: device globals, zero-init)
__device__ float    g_u[B * D];
__device__ float    g_diag[B * D];
__device__ unsigned g_ready[16];   // per-128-col slice: count of finished gates blocks
__device__ unsigned g_done;

__device__ __forceinline__ float sigmoidf(float x) {
    return 1.0f / (1.0f + __expf(-x));
}

__device__ __forceinline__ void finalize_one(
    int b, int i, float dA, float dX,
    const float* __restrict__ xt, const float* __restrict__ h,
    const float* __restrict__ ba, const float* __restrict__ bx,
    const float* __restrict__ Lam)
{
    float rt = sigmoidf(dA + __ldg(ba + i));
    float it = sigmoidf(dX + __ldg(bx + i));
    float la = -log1pf(__expf(-__ldg(Lam + i)));   // -softplus(-Lam)
    float t  = la * rt * 0.125f;                   // /C, C=8
    float a  = __expf(t);
    float om = -expm1f(2.0f * t);                  // 1 - a^2, cancellation-free
    float u  = sqrtf(fmaxf(om, 0.0f)) * it * __ldg(xt + b * D + i);
    g_u[b * D + i]    = u;
    g_diag[b * D + i] = a * __ldg(h + b * D + i);
}

// Split float2 -> (bf16x2 hi, bf16x2 lo residual), packed .b32 each.
__device__ __forceinline__ void cvt_split(float2 w, unsigned& hi, unsigned& lo) {
    __nv_bfloat162 h = __float22bfloat162_rn(w);
    float2 hf = __bfloat1622float2(h);
    float2 r  = make_float2(w.x - hf.x, w.y - hf.y);
    __nv_bfloat162 l = __float22bfloat162_rn(r);
    hi = *reinterpret_cast<unsigned*>(&h);
    lo = *reinterpret_cast<unsigned*>(&l);
}

// D(16x8,f32) += A(16x16,bf16,row) * B(16x8,bf16,col)
__device__ __forceinline__ void mma_bf16(float (&d)[4], const unsigned (&a)[4],
                                         unsigned b0, unsigned b1) {
    asm volatile(
        "mma.sync.aligned.m16n8k16.row.col.f32.bf16.bf16.f32 "
        "{%0,%1,%2,%3}, {%4,%5,%6,%7}, {%8,%9}, {%0,%1,%2,%3};\n"
        : "+f"(d[0]), "+f"(d[1]), "+f"(d[2]), "+f"(d[3])
        : "r"(a[0]), "r"(a[1]), "r"(a[2]), "r"(a[3]), "r"(b0), "r"(b1));
}

// Per-matrix k-step body: load weight pair, split, 3 mmas.
__device__ __forceinline__ void step_mat(
    float (&d)[4], const unsigned (&ahi)[4], const unsigned (&alo)[4],
    const float* wRow, int kg, int qk)
{
    float2 w01 = __ldg(reinterpret_cast<const float2*>(wRow + kg) + qk);
    float2 w89 = __ldg(reinterpret_cast<const float2*>(wRow + kg + 8) + qk);
    unsigned bh0, bl0, bh1, bl1;
    cvt_split(w01, bh0, bl0);
    cvt_split(w89, bh1, bl1);
    mma_bf16(d, ahi, bh0, bh1);
    mma_bf16(d, ahi, bl0, bl1);
    mma_bf16(d, alo, bh0, bh1);
}

// Gates on tensor cores, full-K staging, sync-free mainloop, 2-wave stagger:
//   Grid 256 blocks (2 waves), block = 512 threads (16 warps).
//   Block owns 8 columns n0 = blockIdx.x*8 of BOTH matrices.
//   x (16 x 2048) staged ONCE per block as bf16 hi/lo in 131.6 KB smem.
//   Warp w covers K in [128w, 128w+128) = 8 m16n8k16 k-steps.
//   dot = hi*hi + hi*lo + lo*hi (lo*lo dropped, ~2^-18 relative).
//   On completion: release-fence + atomicAdd(g_ready[slice]) (slice = 128 cols).
__global__ __launch_bounds__(512, 1) void gates_kernel(
    const float* __restrict__ xt, const float* __restrict__ h,
    const float* __restrict__ Wa, const float* __restrict__ Wx,
    const float* __restrict__ ba, const float* __restrict__ bx,
    const float* __restrict__ Lam)
{
    extern __shared__ unsigned smem_raw[];
    unsigned* xs_hi = smem_raw;                    // 16 x 1028 words
    unsigned* xs_lo = smem_raw + B * XPAD;         // 16 x 1028 words
    // rbuf aliases staging storage; only used AFTER the post-mainloop sync.
    float*    rbuf  = reinterpret_cast<float*>(smem_raw);   // 16 x 256 floats

#if __CUDA_ARCH__ >= 900
    cudaTriggerProgrammaticLaunchCompletion();
#endif

    const int tid  = threadIdx.x;
    const int lane = tid & 31;
    const int warp = tid >> 5;
    const int n0   = blockIdx.x * 8;

    const int q  = lane >> 2;     // quad id: A row (batch) / B column
    const int qk = lane & 3;      // k sub-offset

    // ---- prologue: stage all of x as bf16 hi/lo (coalesced float4) ----
    {
        const float4* xt4 = reinterpret_cast<const float4*>(xt);
#pragma unroll
        for (int e = tid; e < B * (D / 4); e += 512) {
            const int row = e >> 9;          // D/4 = 512 float4 per row
            const int c4  = e & 511;
            float4 xv = __ldg(xt4 + row * (D / 4) + c4);
            unsigned h0, l0, h1, l1;
            cvt_split(make_float2(xv.x, xv.y), h0, l0);
            cvt_split(make_float2(xv.z, xv.w), h1, l1);
            const int wb = row * XPAD + 2 * c4;
            xs_hi[wb]     = h0;
            xs_hi[wb + 1] = h1;
            xs_lo[wb]     = l0;
            xs_lo[wb + 1] = l1;
        }
    }
    __syncthreads();

    const float* waR = Wa + (size_t)(n0 + q) * D;
    const float* wxR = Wx + (size_t)(n0 + q) * D;

    float dA[4] = {0.f, 0.f, 0.f, 0.f};
    float dX[4] = {0.f, 0.f, 0.f, 0.f};

    const int kb = 128 * warp;    // this warp's K range: [kb, kb+128)

#pragma unroll 4
    for (int s = 0; s < 8; s++) {
        const int kg = kb + 16 * s;
        const int kw = (kg >> 1) + qk;

        unsigned ahi[4], alo[4];
        {
            const int r0 = q * XPAD;
            const int r1 = (q + 8) * XPAD;
            ahi[0] = xs_hi[r0 + kw];     ahi[1] = xs_hi[r1 + kw];
            ahi[2] = xs_hi[r0 + kw + 4]; ahi[3] = xs_hi[r1 + kw + 4];
            alo[0] = xs_lo[r0 + kw];     alo[1] = xs_lo[r1 + kw];
            alo[2] = xs_lo[r0 + kw + 4]; alo[3] = xs_lo[r1 + kw + 4];
        }

        step_mat(dA, ahi, alo, waR, kg, qk);
        step_mat(dX, ahi, alo, wxR, kg, qk);
    }

    // ---- cross-warp reduction: rbuf[warp][mat*128 + b*8 + col] ----
    __syncthreads();   // staging reads complete everywhere; safe to alias rbuf
    {
        float* rb = rbuf + warp * 256;
        const int c = 2 * qk;
        rb[q * 8 + c]           = dA[0];
        rb[q * 8 + c + 1]       = dA[1];
        rb[(q + 8) * 8 + c]     = dA[2];
        rb[(q + 8) * 8 + c + 1] = dA[3];
        rb[128 + q * 8 + c]           = dX[0];
        rb[128 + q * 8 + c + 1]       = dX[1];
        rb[128 + (q + 8) * 8 + c]     = dX[2];
        rb[128 + (q + 8) * 8 + c + 1] = dX[3];
    }
    __syncthreads();

    if (tid < 128) {
        const int b   = tid >> 3;
        const int col = tid & 7;
        float sA = 0.f, sX = 0.f;
#pragma unroll
        for (int w = 0; w < 16; w++) {
            sA += rbuf[w * 256 + b * 8 + col];
            sX += rbuf[w * 256 + 128 + b * 8 + col];
        }
        finalize_one(b, n0 + col, sA, sX, xt, h, ba, bx, Lam);
    }

    // ---- publish: this block's 8 columns are ready ----
    __threadfence();          // release u/diag to device scope
    __syncthreads();
    if (tid == 0) atomicAdd(&g_ready[blockIdx.x >> 4], 1u);
}

// Writer consumer (launched with PDL): block m -> s = m>>7, b = (m>>3)&15,
// rc = m&7. Writes out[b, rc*256 .. rc*256+256, s*128 .. s*128+128).
__global__ __launch_bounds__(256) void writer_kernel(float* __restrict__ out) {
    const int tid  = threadIdx.x;
    const int lane = tid & 31;
    const int warp = tid >> 5;
    const unsigned m = blockIdx.x;

    const int s  = m >> 7;          // 4 bits: slice
    const int b  = (m >> 3) & 15;   // 4 bits: batch
    const int rc = m & 7;           // 3 bits: 256-row chunk

    if (tid == 0) {
        while (atomicAdd(&g_ready[s], 0u) < 16u) __nanosleep(128);
        __threadfence();            // acquire (observer thread)
    }
    __syncthreads();
    __threadfence();                // acquire fence for all reader threads

    // u segment for this slice: 128 floats, one float4 per lane.
    // __ldcg: coherent L2 load (data may be written during this kernel's
    // lifetime by the overlapped producer).
    const float4 uv = __ldcg(reinterpret_cast<const float4*>(
                                 g_u + (size_t)b * D + s * 128) + lane);
    const float* dgb = g_diag + (size_t)b * D;

    const int i_first = rc * 256 + warp;     // rows: i_first + 8*t, t=0..31
    float* rowp = out + ((size_t)b * D + (size_t)i_first) * D + s * 128;
    int i = i_first;

#pragma unroll 4
    for (int t = 0; t < 32; t++) {
        float4 val = uv;
        const int li = i - s * 128;
        if (li >= 0 && li < 128) {            // diagonal element lives in this tile
            if ((li >> 2) == lane) {
                float dv = __ldcg(dgb + i);
                switch (li & 3) {
                    case 0: val.x += dv; break;
                    case 1: val.y += dv; break;
                    case 2: val.z += dv; break;
                    default: val.w += dv; break;
                }
            }
        }
        __stcs(reinterpret_cast<float4*>(rowp) + lane, val);
        rowp += 8 * D;
        i    += 8;
    }

    // Last writer block resets flags for the next graph replay. Ordered before
    // the next replay's gates by normal stream serialization.
    __syncthreads();
    if (tid == 0) {
        __threadfence();
        unsigned old = atomicAdd(&g_done, 1u);
        if (old == WGRID - 1) {
#pragma unroll
            for (int k = 0; k < 16; k++) g_ready[k] = 0u;
            g_done = 0u;
            __threadfence();
        }
    }
}

extern "C" void kernel_launch(void* const* d_in, const int* in_sizes, int n_in,
                              void* d_out, int out_size) {
    const float* xt  = (const float*)d_in[0];
    const float* h   = (const float*)d_in[1];
    const float* Wa  = (const float*)d_in[2];
    const float* Wx  = (const float*)d_in[3];
    const float* ba  = (const float*)d_in[4];
    const float* bx  = (const float*)d_in[5];
    const float* Lam = (const float*)d_in[6];

    static bool attr_done = false;
    if (!attr_done) {
        cudaFuncSetAttribute(gates_kernel,
                             cudaFuncAttributeMaxDynamicSharedMemorySize,
                             SMEM_BYTES);
        attr_done = true;
    }

    gates_kernel<<<NGBLK, 512, SMEM_BYTES>>>(xt, h, Wa, Wx, ba, bx, Lam);

    // Writer launched with Programmatic Stream Serialization so it can begin
    // while gates is still running; data dependency enforced by g_ready flags.
    cudaLaunchAttribute attr;
    attr.id = cudaLaunchAttributeProgrammaticStreamSerialization;
    attr.val.programmaticStreamSerializationAllowed = 1;

    cudaLaunchConfig_t cfg = {};
    cfg.gridDim  = dim3(WGRID, 1, 1);
    cfg.blockDim = dim3(256, 1, 1);
    cfg.dynamicSmemBytes = 0;
    cfg.stream   = 0;
    cfg.attrs    = &attr;
    cfg.numAttrs = 1;

    float* out = (float*)d_out;
    cudaError_t err = cudaLaunchKernelEx(&cfg, writer_kernel, out);
    if (err != cudaSuccess) {
        // Fallback: plain serialized launch (flags already set by gates)
        writer_kernel<<<WGRID, 256>>>(out);
    }
}

// round 15
// speedup vs baseline: 1.1435x; 1.1435x over previous
#include <cuda_runtime.h>
#include <cuda_bf16.h>

#define D 2048
#define B 16

#define XPAD 1028                  // words per staged x row (conflict-free frags)
#define SMEM_WORDS (2 * B * XPAD)  // rbuf aliases staging (dead after mainloop)
#define SMEM_BYTES (SMEM_WORDS * 4)

// Scratch (allocation-free rule: device globals)
__device__ float g_u[B * D];
__device__ float g_diag[B * D];

__device__ __forceinline__ float sigmoidf(float x) {
    return 1.0f / (1.0f + __expf(-x));
}

__device__ __forceinline__ void finalize_one(
    int b, int i, float dA, float dX,
    const float* __restrict__ xt, const float* __restrict__ h,
    const float* __restrict__ ba, const float* __restrict__ bx,
    const float* __restrict__ Lam)
{
    float rt = sigmoidf(dA + __ldg(ba + i));
    float it = sigmoidf(dX + __ldg(bx + i));
    float la = -log1pf(__expf(-__ldg(Lam + i)));   // -softplus(-Lam)
    float t  = la * rt * 0.125f;                   // /C, C=8
    float a  = __expf(t);
    float om = -expm1f(2.0f * t);                  // 1 - a^2, cancellation-free
    float u  = sqrtf(fmaxf(om, 0.0f)) * it * __ldg(xt + b * D + i);
    g_u[b * D + i]    = u;
    g_diag[b * D + i] = a * __ldg(h + b * D + i);
}

// Split float2 -> (bf16x2 hi, bf16x2 lo residual), packed .b32 each.
__device__ __forceinline__ void cvt_split(float2 w, unsigned& hi, unsigned& lo) {
    __nv_bfloat162 h = __float22bfloat162_rn(w);
    float2 hf = __bfloat1622float2(h);
    float2 r  = make_float2(w.x - hf.x, w.y - hf.y);
    __nv_bfloat162 l = __float22bfloat162_rn(r);
    hi = *reinterpret_cast<unsigned*>(&h);
    lo = *reinterpret_cast<unsigned*>(&l);
}

// D(16x8,f32) += A(16x16,bf16,row) * B(16x8,bf16,col)
__device__ __forceinline__ void mma_bf16(float (&d)[4], const unsigned (&a)[4],
                                         unsigned b0, unsigned b1) {
    asm volatile(
        "mma.sync.aligned.m16n8k16.row.col.f32.bf16.bf16.f32 "
        "{%0,%1,%2,%3}, {%4,%5,%6,%7}, {%8,%9}, {%0,%1,%2,%3};\n"
        : "+f"(d[0]), "+f"(d[1]), "+f"(d[2]), "+f"(d[3])
        : "r"(a[0]), "r"(a[1]), "r"(a[2]), "r"(a[3]), "r"(b0), "r"(b1));
}

// Convert a loaded weight pair and run the 3-term split mma into d.
__device__ __forceinline__ void cvt_mma(
    float (&d)[4], const unsigned (&ahi)[4], const unsigned (&alo)[4],
    float2 w01, float2 w89)
{
    unsigned bh0, bl0, bh1, bl1;
    cvt_split(w01, bh0, bl0);
    cvt_split(w89, bh1, bl1);
    mma_bf16(d, ahi, bh0, bh1);
    mma_bf16(d, ahi, bl0, bl1);
    mma_bf16(d, alo, bh0, bh1);
}

// Gates on tensor cores, full-K staging, sync-free mainloop:
//   Grid 128 blocks (single wave, 1 block/SM), block = 512 threads (16 warps).
//   Block owns 16 columns n0 = blockIdx.x*16 of BOTH matrices.
//   x (16 x 2048) staged ONCE as bf16 hi/lo in 131.6 KB smem.
//   Warp w covers K in [128w, 128w+128) = 8 m16n8k16 k-steps.
//   All 8 weight LDGs of a k-step are issued BEFORE any convert/mma
//   (front-batched MLP; with unroll 4 that's ~32 loads in flight).
//   dot = hi*hi + hi*lo + lo*hi (lo*lo dropped, ~2^-18 relative).
__global__ __launch_bounds__(512, 1) void gates_kernel(
    const float* __restrict__ xt, const float* __restrict__ h,
    const float* __restrict__ Wa, const float* __restrict__ Wx,
    const float* __restrict__ ba, const float* __restrict__ bx,
    const float* __restrict__ Lam)
{
    extern __shared__ unsigned smem_raw[];
    unsigned* xs_hi = smem_raw;                    // 16 x 1028 words
    unsigned* xs_lo = smem_raw + B * XPAD;         // 16 x 1028 words
    // rbuf aliases staging storage; only used AFTER the post-mainloop sync.
    float*    rbuf  = reinterpret_cast<float*>(smem_raw);   // 16 x 512 floats

    const int tid  = threadIdx.x;
    const int lane = tid & 31;
    const int warp = tid >> 5;
    const int n0   = blockIdx.x * 16;

    const int q  = lane >> 2;     // quad id: A row / B column
    const int qk = lane & 3;      // k sub-offset

    // ---- prologue: stage all of x as bf16 hi/lo (coalesced float4) ----
    {
        const float4* xt4 = reinterpret_cast<const float4*>(xt);
#pragma unroll
        for (int e = tid; e < B * (D / 4); e += 512) {
            const int row = e >> 9;          // D/4 = 512 float4 per row
            const int c4  = e & 511;
            float4 xv = __ldg(xt4 + row * (D / 4) + c4);
            unsigned h0, l0, h1, l1;
            cvt_split(make_float2(xv.x, xv.y), h0, l0);
            cvt_split(make_float2(xv.z, xv.w), h1, l1);
            const int wb = row * XPAD + 2 * c4;
            xs_hi[wb]     = h0;
            xs_hi[wb + 1] = h1;
            xs_lo[wb]     = l0;
            xs_lo[wb + 1] = l1;
        }
    }
    __syncthreads();

    // Weight row pointers: group 0 -> col n0+q, group 1 -> col n0+8+q.
    const float* waR0 = Wa + (size_t)(n0 + q) * D;
    const float* waR1 = Wa + (size_t)(n0 + 8 + q) * D;
    const float* wxR0 = Wx + (size_t)(n0 + q) * D;
    const float* wxR1 = Wx + (size_t)(n0 + 8 + q) * D;

    float dA0[4] = {0.f, 0.f, 0.f, 0.f};
    float dA1[4] = {0.f, 0.f, 0.f, 0.f};
    float dX0[4] = {0.f, 0.f, 0.f, 0.f};
    float dX1[4] = {0.f, 0.f, 0.f, 0.f};

    const int kb = 128 * warp;    // this warp's K range: [kb, kb+128)

#pragma unroll 4
    for (int s = 0; s < 8; s++) {
        const int kg = kb + 16 * s;
        const int kw = (kg >> 1) + qk;

        // ---- front-batch ALL weight loads for this k-step (8 LDG.64) ----
        float2 a0_01 = __ldg(reinterpret_cast<const float2*>(waR0 + kg) + qk);
        float2 a0_89 = __ldg(reinterpret_cast<const float2*>(waR0 + kg + 8) + qk);
        float2 a1_01 = __ldg(reinterpret_cast<const float2*>(waR1 + kg) + qk);
        float2 a1_89 = __ldg(reinterpret_cast<const float2*>(waR1 + kg + 8) + qk);
        float2 x0_01 = __ldg(reinterpret_cast<const float2*>(wxR0 + kg) + qk);
        float2 x0_89 = __ldg(reinterpret_cast<const float2*>(wxR0 + kg + 8) + qk);
        float2 x1_01 = __ldg(reinterpret_cast<const float2*>(wxR1 + kg) + qk);
        float2 x1_89 = __ldg(reinterpret_cast<const float2*>(wxR1 + kg + 8) + qk);

        // ---- A fragments from smem ----
        unsigned ahi[4], alo[4];
        {
            const int r0 = q * XPAD;
            const int r1 = (q + 8) * XPAD;
            ahi[0] = xs_hi[r0 + kw];     ahi[1] = xs_hi[r1 + kw];
            ahi[2] = xs_hi[r0 + kw + 4]; ahi[3] = xs_hi[r1 + kw + 4];
            alo[0] = xs_lo[r0 + kw];     alo[1] = xs_lo[r1 + kw];
            alo[2] = xs_lo[r0 + kw + 4]; alo[3] = xs_lo[r1 + kw + 4];
        }

        // ---- converts + mmas (consume loads in issue order) ----
        cvt_mma(dA0, ahi, alo, a0_01, a0_89);
        cvt_mma(dA1, ahi, alo, a1_01, a1_89);
        cvt_mma(dX0, ahi, alo, x0_01, x0_89);
        cvt_mma(dX1, ahi, alo, x1_01, x1_89);
    }

    // ---- cross-warp reduction: rbuf[warp][mat*256 + b*16 + col] ----
    __syncthreads();   // staging reads complete everywhere; safe to alias rbuf
    {
        float* rb = rbuf + warp * 512;
        const int c = 2 * qk;
#pragma unroll
        for (int g = 0; g < 2; g++) {
            const float* dA = g ? dA1 : dA0;
            const float* dX = g ? dX1 : dX0;
            const int col = 8 * g + c;
            rb[q * 16 + col]             = dA[0];
            rb[q * 16 + col + 1]         = dA[1];
            rb[(q + 8) * 16 + col]       = dA[2];
            rb[(q + 8) * 16 + col + 1]   = dA[3];
            rb[256 + q * 16 + col]           = dX[0];
            rb[256 + q * 16 + col + 1]       = dX[1];
            rb[256 + (q + 8) * 16 + col]     = dX[2];
            rb[256 + (q + 8) * 16 + col + 1] = dX[3];
        }
    }
    __syncthreads();

    if (tid < 256) {
        const int b   = tid >> 4;
        const int col = tid & 15;
        float sA = 0.f, sX = 0.f;
#pragma unroll
        for (int w = 0; w < 16; w++) {
            sA += rbuf[w * 512 + b * 16 + col];
            sX += rbuf[w * 512 + 256 + b * 16 + col];
        }
        finalize_one(b, n0 + col, sA, sX, xt, h, ba, bx, Lam);
    }
}

// Writer: ht[b,i,j] = u[b,j] + (i==j)*diag[b,i].
// Block = (batch b, 16 consecutive rows i). u row held in registers
// (2 float4 / thread, 256 threads = 2048 floats). Streaming stores.
__global__ __launch_bounds__(256) void writer_kernel(float* __restrict__ out) {
    const int b   = blockIdx.y;
    const int i0  = blockIdx.x * 16;
    const int tid = threadIdx.x;

    const float4* u4 = reinterpret_cast<const float4*>(g_u + b * D);
    const float4  va = __ldg(u4 + tid);
    const float4  vb = __ldg(u4 + tid + 256);
    const float*  dg = g_diag + b * D;

    float* obase = out + ((size_t)b * D + (size_t)i0) * D;

#pragma unroll 4
    for (int r = 0; r < 16; r++) {
        const int i  = i0 + r;
        const float dv = __ldg(dg + i);
        float4 sa = va, sb = vb;
        const int qq = i >> 2, c = i & 3;
        if (qq == tid) {
            if      (c == 0) sa.x += dv;
            else if (c == 1) sa.y += dv;
            else if (c == 2) sa.z += dv;
            else             sa.w += dv;
        } else if (qq - 256 == tid) {
            if      (c == 0) sb.x += dv;
            else if (c == 1) sb.y += dv;
            else if (c == 2) sb.z += dv;
            else             sb.w += dv;
        }
        float4* orow = reinterpret_cast<float4*>(obase + (size_t)r * D);
        __stcs(orow + tid, sa);
        __stcs(orow + tid + 256, sb);
    }
}

extern "C" void kernel_launch(void* const* d_in, const int* in_sizes, int n_in,
                              void* d_out, int out_size) {
    const float* xt  = (const float*)d_in[0];
    const float* h   = (const float*)d_in[1];
    const float* Wa  = (const float*)d_in[2];
    const float* Wx  = (const float*)d_in[3];
    const float* ba  = (const float*)d_in[4];
    const float* bx  = (const float*)d_in[5];
    const float* Lam = (const float*)d_in[6];

    static bool attr_done = false;
    if (!attr_done) {
        cudaFuncSetAttribute(gates_kernel,
                             cudaFuncAttributeMaxDynamicSharedMemorySize,
                             SMEM_BYTES);
        attr_done = true;
    }

    gates_kernel<<<128, 512, SMEM_BYTES>>>(xt, h, Wa, Wx, ba, bx, Lam);

    dim3 grid(D / 16, B);
    writer_kernel<<<grid, 256>>>((float*)d_out);
}

// round 16
// speedup vs baseline: 1.1481x; 1.0041x over previous
#include <cuda_runtime.h>
#include <cuda_bf16.h>

#define D 2048
#define B 16

#define XPAD 1028                       // words per staged x row
#define STAGES 4
#define NCHUNK 16                       // K chunks of 128
#define WROWS 32                        // 16 cols x 2 matrices
#define WSTRIDE 136                     // words per weight row (128 + 8 pad)
#define WSTAGE_WORDS (WROWS * WSTRIDE)  // 4352
#define X_WORDS (2 * B * XPAD)          // 32896
#define SMEM_WORDS (X_WORDS + STAGES * WSTAGE_WORDS)
#define SMEM_BYTES (SMEM_WORDS * 4)     // 201216 B

// Scratch (allocation-free rule: device globals)
__device__ float g_u[B * D];
__device__ float g_diag[B * D];

__device__ __forceinline__ float sigmoidf(float x) {
    return 1.0f / (1.0f + __expf(-x));
}

__device__ __forceinline__ void finalize_one(
    int b, int i, float dA, float dX,
    const float* __restrict__ xt, const float* __restrict__ h,
    const float* __restrict__ ba, const float* __restrict__ bx,
    const float* __restrict__ Lam)
{
    float rt = sigmoidf(dA + __ldg(ba + i));
    float it = sigmoidf(dX + __ldg(bx + i));
    float la = -log1pf(__expf(-__ldg(Lam + i)));   // -softplus(-Lam)
    float t  = la * rt * 0.125f;                   // /C, C=8
    float a  = __expf(t);
    float om = -expm1f(2.0f * t);                  // 1 - a^2, cancellation-free
    float u  = sqrtf(fmaxf(om, 0.0f)) * it * __ldg(xt + b * D + i);
    g_u[b * D + i]    = u;
    g_diag[b * D + i] = a * __ldg(h + b * D + i);
}

// Split float2 -> (bf16x2 hi, bf16x2 lo residual), packed .b32 each.
__device__ __forceinline__ void cvt_split(float2 w, unsigned& hi, unsigned& lo) {
    __nv_bfloat162 h = __float22bfloat162_rn(w);
    float2 hf = __bfloat1622float2(h);
    float2 r  = make_float2(w.x - hf.x, w.y - hf.y);
    __nv_bfloat162 l = __float22bfloat162_rn(r);
    hi = *reinterpret_cast<unsigned*>(&h);
    lo = *reinterpret_cast<unsigned*>(&l);
}

// D(16x8,f32) += A(16x16,bf16,row) * B(16x8,bf16,col)
__device__ __forceinline__ void mma_bf16(float (&d)[4], const unsigned (&a)[4],
                                         unsigned b0, unsigned b1) {
    asm volatile(
        "mma.sync.aligned.m16n8k16.row.col.f32.bf16.bf16.f32 "
        "{%0,%1,%2,%3}, {%4,%5,%6,%7}, {%8,%9}, {%0,%1,%2,%3};\n"
        : "+f"(d[0]), "+f"(d[1]), "+f"(d[2]), "+f"(d[3])
        : "r"(a[0]), "r"(a[1]), "r"(a[2]), "r"(a[3]), "r"(b0), "r"(b1));
}

// Convert a loaded weight pair and run the 3-term split mma into d.
__device__ __forceinline__ void cvt_mma(
    float (&d)[4], const unsigned (&ahi)[4], const unsigned (&alo)[4],
    float2 w01, float2 w89)
{
    unsigned bh0, bl0, bh1, bl1;
    cvt_split(w01, bh0, bl0);
    cvt_split(w89, bh1, bl1);
    mma_bf16(d, ahi, bh0, bh1);
    mma_bf16(d, ahi, bl0, bl1);
    mma_bf16(d, alo, bh0, bh1);
}

// Issue the cp.async copies for weight chunk c into ring stage `stage`.
// 512 threads x 2 x 16B = 16 KB: rows 0..15 = Wa cols n0..n0+15, 16..31 = Wx.
__device__ __forceinline__ void issue_chunk(
    unsigned* wring, int stage, int c, int tid, int n0,
    const float* __restrict__ Wa, const float* __restrict__ Wx)
{
    const int r   = tid >> 5;           // 0..15: column index within block
    const int off = (tid & 31) * 4;     // word offset within 128-float row chunk
    unsigned* sbase = wring + stage * WSTAGE_WORDS;
    {
        const float* g = Wa + (size_t)(n0 + r) * D + 128 * c + off;
        unsigned sa = (unsigned)__cvta_generic_to_shared(sbase + r * WSTRIDE + off);
        asm volatile("cp.async.cg.shared.global [%0], [%1], 16;\n" :: "r"(sa), "l"(g));
    }
    {
        const float* g = Wx + (size_t)(n0 + r) * D + 128 * c + off;
        unsigned sa = (unsigned)__cvta_generic_to_shared(sbase + (16 + r) * WSTRIDE + off);
        asm volatile("cp.async.cg.shared.global [%0], [%1], 16;\n" :: "r"(sa), "l"(g));
    }
}

// Gates on tensor cores with cp.async weight pipeline:
//   Grid 128 (single wave, 1 block/SM), block 512 threads (16 warps).
//   Block owns 16 cols n0 = blockIdx.x*16 of BOTH matrices.
//   x staged once as bf16 hi/lo (131.6 KB). Weights stream through a 4-stage
//   smem ring via coalesced cp.async (16 KB chunks = 128 K x 32 rows).
//   Per chunk: warp w -> k-step w>>1, matrix w&1, both column groups.
//   dot = hi*hi + hi*lo + lo*hi (lo*lo dropped, ~2^-18 relative).
__global__ __launch_bounds__(512, 1) void gates_kernel(
    const float* __restrict__ xt, const float* __restrict__ h,
    const float* __restrict__ Wa, const float* __restrict__ Wx,
    const float* __restrict__ ba, const float* __restrict__ bx,
    const float* __restrict__ Lam)
{
    extern __shared__ unsigned smem_raw[];
    unsigned* xs_hi = smem_raw;                    // 16 x 1028 words
    unsigned* xs_lo = smem_raw + B * XPAD;         // 16 x 1028 words
    unsigned* wring = smem_raw + X_WORDS;          // 4 x 4352 words
    float*    rbuf  = reinterpret_cast<float*>(smem_raw);   // aliases x (epilogue)

    const int tid  = threadIdx.x;
    const int lane = tid & 31;
    const int warp = tid >> 5;
    const int n0   = blockIdx.x * 16;

    const int q  = lane >> 2;     // quad id: A row (batch) / B column
    const int qk = lane & 3;      // k sub-offset

    // ---- kick off the first STAGES weight chunks (overlaps x staging) ----
#pragma unroll
    for (int c = 0; c < STAGES; c++) {
        issue_chunk(wring, c, c, tid, n0, Wa, Wx);
        asm volatile("cp.async.commit_group;\n" ::: "memory");
    }

    // ---- prologue: stage all of x as bf16 hi/lo (coalesced float4) ----
    {
        const float4* xt4 = reinterpret_cast<const float4*>(xt);
#pragma unroll
        for (int e = tid; e < B * (D / 4); e += 512) {
            const int row = e >> 9;          // D/4 = 512 float4 per row
            const int c4  = e & 511;
            float4 xv = __ldg(xt4 + row * (D / 4) + c4);
            unsigned h0, l0, h1, l1;
            cvt_split(make_float2(xv.x, xv.y), h0, l0);
            cvt_split(make_float2(xv.z, xv.w), h1, l1);
            const int wb = row * XPAD + 2 * c4;
            xs_hi[wb]     = h0;
            xs_hi[wb + 1] = h1;
            xs_lo[wb]     = l0;
            xs_lo[wb + 1] = l1;
        }
    }
    __syncthreads();

    const int mat = warp & 1;     // 0 = Wa, 1 = Wx
    const int kl  = warp >> 1;    // k-step within chunk: 0..7

    float d0[4] = {0.f, 0.f, 0.f, 0.f};   // column group 0 (cols n0 + q)
    float d1[4] = {0.f, 0.f, 0.f, 0.f};   // column group 1 (cols n0 + 8 + q)

#pragma unroll 4
    for (int c = 0; c < NCHUNK; c++) {
        asm volatile("cp.async.wait_group 3;\n" ::: "memory");
        __syncthreads();

        // ---- A fragments for k = 128c + 16*kl ----
        unsigned ahi[4], alo[4];
        {
            const int kw = 64 * c + 8 * kl + qk;
            const int r0 = q * XPAD;
            const int r1 = (q + 8) * XPAD;
            ahi[0] = xs_hi[r0 + kw];     ahi[1] = xs_hi[r1 + kw];
            ahi[2] = xs_hi[r0 + kw + 4]; ahi[3] = xs_hi[r1 + kw + 4];
            alo[0] = xs_lo[r0 + kw];     alo[1] = xs_lo[r1 + kw];
            alo[2] = xs_lo[r0 + kw + 4]; alo[3] = xs_lo[r1 + kw + 4];
        }

        // ---- weight fragments from the ring (conflict-free LDS.64) ----
        const unsigned* sb = wring + (c & 3) * WSTAGE_WORDS;
        {
            const int rloc = mat * 16 + q;           // column group 0
            const float* wr = reinterpret_cast<const float*>(sb) + rloc * WSTRIDE + 16 * kl;
            float2 w01 = *reinterpret_cast<const float2*>(wr + 2 * qk);
            float2 w89 = *reinterpret_cast<const float2*>(wr + 8 + 2 * qk);
            cvt_mma(d0, ahi, alo, w01, w89);
        }
        {
            const int rloc = mat * 16 + 8 + q;       // column group 1
            const float* wr = reinterpret_cast<const float*>(sb) + rloc * WSTRIDE + 16 * kl;
            float2 w01 = *reinterpret_cast<const float2*>(wr + 2 * qk);
            float2 w89 = *reinterpret_cast<const float2*>(wr + 8 + 2 * qk);
            cvt_mma(d1, ahi, alo, w01, w89);
        }

        __syncthreads();    // everyone done reading stage (c&3) before overwrite

        if (c + STAGES < NCHUNK) {
            issue_chunk(wring, c & 3, c + STAGES, tid, n0, Wa, Wx);
        }
        asm volatile("cp.async.commit_group;\n" ::: "memory");  // (empty in tail)
    }

    // ---- epilogue: combine (mat, cg, kstep) partials ----
    __syncthreads();   // x staging dead; safe to alias rbuf
    {
        // slot = warp*2 + cg, element = b*8 + col
        float* rb = rbuf + (warp * 2 + 0) * 128;
        rb[q * 8 + 2 * qk]           = d0[0];
        rb[q * 8 + 2 * qk + 1]       = d0[1];
        rb[(q + 8) * 8 + 2 * qk]     = d0[2];
        rb[(q + 8) * 8 + 2 * qk + 1] = d0[3];
        rb = rbuf + (warp * 2 + 1) * 128;
        rb[q * 8 + 2 * qk]           = d1[0];
        rb[q * 8 + 2 * qk + 1]       = d1[1];
        rb[(q + 8) * 8 + 2 * qk]     = d1[2];
        rb[(q + 8) * 8 + 2 * qk + 1] = d1[3];
    }
    __syncthreads();

    if (tid < 256) {
        const int b   = tid >> 4;
        const int c16 = tid & 15;
        const int cg  = c16 >> 3;
        const int col = c16 & 7;
        float sA = 0.f, sX = 0.f;
#pragma unroll
        for (int j = 0; j < 8; j++) {
            // mat A partials: warps 2j (slots 4j+cg); mat X: warps 2j+1 (4j+2+cg)
            sA += rbuf[(4 * j + cg) * 128 + b * 8 + col];
            sX += rbuf[(4 * j + 2 + cg) * 128 + b * 8 + col];
        }
        finalize_one(b, n0 + c16, sA, sX, xt, h, ba, bx, Lam);
    }
}

// Writer: ht[b,i,j] = u[b,j] + (i==j)*diag[b,i].
// Block = (batch b, 16 consecutive rows i). u row held in registers
// (2 float4 / thread, 256 threads = 2048 floats). Streaming stores.
__global__ __launch_bounds__(256) void writer_kernel(float* __restrict__ out) {
    const int b   = blockIdx.y;
    const int i0  = blockIdx.x * 16;
    const int tid = threadIdx.x;

    const float4* u4 = reinterpret_cast<const float4*>(g_u + b * D);
    const float4  va = __ldg(u4 + tid);
    const float4  vb = __ldg(u4 + tid + 256);
    const float*  dg = g_diag + b * D;

    float* obase = out + ((size_t)b * D + (size_t)i0) * D;

#pragma unroll 4
    for (int r = 0; r < 16; r++) {
        const int i  = i0 + r;
        const float dv = __ldg(dg + i);
        float4 sa = va, sb = vb;
        const int qq = i >> 2, c = i & 3;
        if (qq == tid) {
            if      (c == 0) sa.x += dv;
            else if (c == 1) sa.y += dv;
            else if (c == 2) sa.z += dv;
            else             sa.w += dv;
        } else if (qq - 256 == tid) {
            if      (c == 0) sb.x += dv;
            else if (c == 1) sb.y += dv;
            else if (c == 2) sb.z += dv;
            else             sb.w += dv;
        }
        float4* orow = reinterpret_cast<float4*>(obase + (size_t)r * D);
        __stcs(orow + tid, sa);
        __stcs(orow + tid + 256, sb);
    }
}

extern "C" void kernel_launch(void* const* d_in, const int* in_sizes, int n_in,
                              void* d_out, int out_size) {
    const float* xt  = (const float*)d_in[0];
    const float* h   = (const float*)d_in[1];
    const float* Wa  = (const float*)d_in[2];
    const float* Wx  = (const float*)d_in[3];
    const float* ba  = (const float*)d_in[4];
    const float* bx  = (const float*)d_in[5];
    const float* Lam = (const float*)d_in[6];

    static bool attr_done = false;
    if (!attr_done) {
        cudaFuncSetAttribute(gates_kernel,
                             cudaFuncAttributeMaxDynamicSharedMemorySize,
                             SMEM_BYTES);
        attr_done = true;
    }

    gates_kernel<<<128, 512, SMEM_BYTES>>>(xt, h, Wa, Wx, ba, bx, Lam);

    dim3 grid(D / 16, B);
    writer_kernel<<<grid, 256>>>((float*)d_out);
}

// round 17
// speedup vs baseline: 1.1488x; 1.0006x over previous
#include <cuda_runtime.h>
#include <cuda_bf16.h>

#define D 2048
#define B 16

#define XPAD 1028                       // words per staged x row
#define STAGES 2
#define NCHUNK 8                        // K chunks of 256
#define WROWS 32                        // 16 cols x 2 matrices
#define WSTRIDE 264                     // words per weight row chunk (256 + 8 pad)
#define WSTAGE_WORDS (WROWS * WSTRIDE)  // 8448
#define X_WORDS (2 * B * XPAD)          // 32896
#define SMEM_WORDS (X_WORDS + STAGES * WSTAGE_WORDS)
#define SMEM_BYTES (SMEM_WORDS * 4)     // 199168 B

// Scratch (allocation-free rule: device globals)
__device__ float g_u[B * D];
__device__ float g_diag[B * D];

__device__ __forceinline__ float sigmoidf(float x) {
    return 1.0f / (1.0f + __expf(-x));
}

__device__ __forceinline__ void finalize_one(
    int b, int i, float dA, float dX,
    const float* __restrict__ xt, const float* __restrict__ h,
    const float* __restrict__ ba, const float* __restrict__ bx,
    const float* __restrict__ Lam)
{
    float rt = sigmoidf(dA + __ldg(ba + i));
    float it = sigmoidf(dX + __ldg(bx + i));
    float la = -log1pf(__expf(-__ldg(Lam + i)));   // -softplus(-Lam)
    float t  = la * rt * 0.125f;                   // /C, C=8
    float a  = __expf(t);
    float om = -expm1f(2.0f * t);                  // 1 - a^2, cancellation-free
    float u  = sqrtf(fmaxf(om, 0.0f)) * it * __ldg(xt + b * D + i);
    g_u[b * D + i]    = u;
    g_diag[b * D + i] = a * __ldg(h + b * D + i);
}

// Split float2 -> (bf16x2 hi, bf16x2 lo residual), packed .b32 each.
__device__ __forceinline__ void cvt_split(float2 w, unsigned& hi, unsigned& lo) {
    __nv_bfloat162 h = __float22bfloat162_rn(w);
    float2 hf = __bfloat1622float2(h);
    float2 r  = make_float2(w.x - hf.x, w.y - hf.y);
    __nv_bfloat162 l = __float22bfloat162_rn(r);
    hi = *reinterpret_cast<unsigned*>(&h);
    lo = *reinterpret_cast<unsigned*>(&l);
}

// D(16x8,f32) += A(16x16,bf16,row) * B(16x8,bf16,col)
__device__ __forceinline__ void mma_bf16(float (&d)[4], const unsigned (&a)[4],
                                         unsigned b0, unsigned b1) {
    asm volatile(
        "mma.sync.aligned.m16n8k16.row.col.f32.bf16.bf16.f32 "
        "{%0,%1,%2,%3}, {%4,%5,%6,%7}, {%8,%9}, {%0,%1,%2,%3};\n"
        : "+f"(d[0]), "+f"(d[1]), "+f"(d[2]), "+f"(d[3])
        : "r"(a[0]), "r"(a[1]), "r"(a[2]), "r"(a[3]), "r"(b0), "r"(b1));
}

// Convert a loaded weight pair and run the 3-term split mma into d.
__device__ __forceinline__ void cvt_mma(
    float (&d)[4], const unsigned (&ahi)[4], const unsigned (&alo)[4],
    float2 w01, float2 w89)
{
    unsigned bh0, bl0, bh1, bl1;
    cvt_split(w01, bh0, bl0);
    cvt_split(w89, bh1, bl1);
    mma_bf16(d, ahi, bh0, bh1);
    mma_bf16(d, ahi, bl0, bl1);
    mma_bf16(d, alo, bh0, bh1);
}

// Issue cp.async copies for a 256-K weight chunk c into ring stage `stage`.
// 32 rows (16 Wa cols, 16 Wx cols) x 1 KB. 512 threads x 4 x 16B, coalesced.
__device__ __forceinline__ void issue_chunk(
    unsigned* wring, int stage, int c, int tid, int n0,
    const float* __restrict__ Wa, const float* __restrict__ Wx)
{
    unsigned* sbase = wring + stage * WSTAGE_WORDS;
#pragma unroll
    for (int j = 0; j < 4; j++) {
        const int e   = tid + 512 * j;        // 0..2047
        const int row = e >> 6;               // 0..31
        const int off = (e & 63) * 4;         // word offset within 256-float chunk
        const float* g = (row < 16 ? Wa + (size_t)(n0 + row) * D
                                   : Wx + (size_t)(n0 + row - 16) * D)
                         + 256 * c + off;
        unsigned sa = (unsigned)__cvta_generic_to_shared(sbase + row * WSTRIDE + off);
        asm volatile("cp.async.cg.shared.global [%0], [%1], 16;\n" :: "r"(sa), "l"(g));
    }
}

// Gates on tensor cores with double-buffered 256-K cp.async weight pipeline:
//   Grid 128 (single wave, 1 block/SM), block 512 threads (16 warps).
//   Block owns 16 cols n0 = blockIdx.x*16 of BOTH matrices.
//   x staged once as bf16 hi/lo (131.6 KB). Weights stream through a 2-stage
//   smem ring via coalesced cp.async (32 KB chunks). 16 syncs total.
//   Per chunk: warp w -> matrix w&1, k-step pair w>>1 (2 steps, both cgs).
//   dot = hi*hi + hi*lo + lo*hi (lo*lo dropped, ~2^-18 relative).
__global__ __launch_bounds__(512, 1) void gates_kernel(
    const float* __restrict__ xt, const float* __restrict__ h,
    const float* __restrict__ Wa, const float* __restrict__ Wx,
    const float* __restrict__ ba, const float* __restrict__ bx,
    const float* __restrict__ Lam)
{
    extern __shared__ unsigned smem_raw[];
    unsigned* xs_hi = smem_raw;                    // 16 x 1028 words
    unsigned* xs_lo = smem_raw + B * XPAD;         // 16 x 1028 words
    unsigned* wring = smem_raw + X_WORDS;          // 2 x 8448 words
    float*    rbuf  = reinterpret_cast<float*>(smem_raw);   // aliases x (epilogue)

    const int tid  = threadIdx.x;
    const int lane = tid & 31;
    const int warp = tid >> 5;
    const int n0   = blockIdx.x * 16;

    const int q  = lane >> 2;     // quad id: A row (batch) / B column
    const int qk = lane & 3;      // k sub-offset

    // ---- prefetch chunk 0 (overlaps the x-conversion prologue) ----
    issue_chunk(wring, 0, 0, tid, n0, Wa, Wx);
    asm volatile("cp.async.commit_group;\n" ::: "memory");

    // ---- prologue: stage all of x as bf16 hi/lo (coalesced float4) ----
    {
        const float4* xt4 = reinterpret_cast<const float4*>(xt);
#pragma unroll
        for (int e = tid; e < B * (D / 4); e += 512) {
            const int row = e >> 9;          // D/4 = 512 float4 per row
            const int c4  = e & 511;
            float4 xv = __ldg(xt4 + row * (D / 4) + c4);
            unsigned h0, l0, h1, l1;
            cvt_split(make_float2(xv.x, xv.y), h0, l0);
            cvt_split(make_float2(xv.z, xv.w), h1, l1);
            const int wb = row * XPAD + 2 * c4;
            xs_hi[wb]     = h0;
            xs_hi[wb + 1] = h1;
            xs_lo[wb]     = l0;
            xs_lo[wb + 1] = l1;
        }
    }
    __syncthreads();

    const int mat   = warp & 1;   // 0 = Wa, 1 = Wx
    const int kpair = warp >> 1;  // 0..7: k-step pair within chunk

    float d0[4] = {0.f, 0.f, 0.f, 0.f};   // column group 0 (cols n0 + q)
    float d1[4] = {0.f, 0.f, 0.f, 0.f};   // column group 1 (cols n0 + 8 + q)

    for (int c = 0; c < NCHUNK; c++) {
        // Prefetch next chunk into the other stage, then wait for chunk c.
        if (c + 1 < NCHUNK) {
            issue_chunk(wring, (c + 1) & 1, c + 1, tid, n0, Wa, Wx);
        }
        asm volatile("cp.async.commit_group;\n" ::: "memory");
        asm volatile("cp.async.wait_group 1;\n" ::: "memory");
        __syncthreads();

        const float* stF = reinterpret_cast<const float*>(wring + (c & 1) * WSTAGE_WORDS);

#pragma unroll
        for (int s2 = 0; s2 < 2; s2++) {
            const int kl = 2 * kpair + s2;        // k-step within chunk: 0..15

            // ---- A fragments for k = 256c + 16*kl ----
            unsigned ahi[4], alo[4];
            {
                const int kw = 128 * c + 8 * kl + qk;
                const int r0 = q * XPAD;
                const int r1 = (q + 8) * XPAD;
                ahi[0] = xs_hi[r0 + kw];     ahi[1] = xs_hi[r1 + kw];
                ahi[2] = xs_hi[r0 + kw + 4]; ahi[3] = xs_hi[r1 + kw + 4];
                alo[0] = xs_lo[r0 + kw];     alo[1] = xs_lo[r1 + kw];
                alo[2] = xs_lo[r0 + kw + 4]; alo[3] = xs_lo[r1 + kw + 4];
            }

            // ---- weight fragments from the ring ----
            {
                const float* wr = stF + (mat * 16 + q) * WSTRIDE + 16 * kl;
                float2 w01 = *reinterpret_cast<const float2*>(wr + 2 * qk);
                float2 w89 = *reinterpret_cast<const float2*>(wr + 8 + 2 * qk);
                cvt_mma(d0, ahi, alo, w01, w89);
            }
            {
                const float* wr = stF + (mat * 16 + 8 + q) * WSTRIDE + 16 * kl;
                float2 w01 = *reinterpret_cast<const float2*>(wr + 2 * qk);
                float2 w89 = *reinterpret_cast<const float2*>(wr + 8 + 2 * qk);
                cvt_mma(d1, ahi, alo, w01, w89);
            }
        }

        __syncthreads();    // all reads of stage (c&1) done before it is refilled
    }

    // ---- epilogue: combine (mat, cg, kpair) partials ----
    // x staging dead (last chunk consumed); safe to alias rbuf.
    {
        float* rb = rbuf + (warp * 2 + 0) * 128;
        rb[q * 8 + 2 * qk]           = d0[0];
        rb[q * 8 + 2 * qk + 1]       = d0[1];
        rb[(q + 8) * 8 + 2 * qk]     = d0[2];
        rb[(q + 8) * 8 + 2 * qk + 1] = d0[3];
        rb = rbuf + (warp * 2 + 1) * 128;
        rb[q * 8 + 2 * qk]           = d1[0];
        rb[q * 8 + 2 * qk + 1]       = d1[1];
        rb[(q + 8) * 8 + 2 * qk]     = d1[2];
        rb[(q + 8) * 8 + 2 * qk + 1] = d1[3];
    }
    __syncthreads();

    if (tid < 256) {
        const int b   = tid >> 4;
        const int c16 = tid & 15;
        const int cg  = c16 >> 3;
        const int col = c16 & 7;
        float sA = 0.f, sX = 0.f;
#pragma unroll
        for (int j = 0; j < 8; j++) {
            // mat A partials: warps 2j (slots 4j+cg); mat X: warps 2j+1 (4j+2+cg)
            sA += rbuf[(4 * j + cg) * 128 + b * 8 + col];
            sX += rbuf[(4 * j + 2 + cg) * 128 + b * 8 + col];
        }
        finalize_one(b, n0 + c16, sA, sX, xt, h, ba, bx, Lam);
    }
}

// Writer: ht[b,i,j] = u[b,j] + (i==j)*diag[b,i].
// Block = (batch b, 16 consecutive rows i). u row held in registers
// (2 float4 / thread, 256 threads = 2048 floats). Streaming stores.
__global__ __launch_bounds__(256) void writer_kernel(float* __restrict__ out) {
    const int b   = blockIdx.y;
    const int i0  = blockIdx.x * 16;
    const int tid = threadIdx.x;

    const float4* u4 = reinterpret_cast<const float4*>(g_u + b * D);
    const float4  va = __ldg(u4 + tid);
    const float4  vb = __ldg(u4 + tid + 256);
    const float*  dg = g_diag + b * D;

    float* obase = out + ((size_t)b * D + (size_t)i0) * D;

#pragma unroll 4
    for (int r = 0; r < 16; r++) {
        const int i  = i0 + r;
        const float dv = __ldg(dg + i);
        float4 sa = va, sb = vb;
        const int qq = i >> 2, c = i & 3;
        if (qq == tid) {
            if      (c == 0) sa.x += dv;
            else if (c == 1) sa.y += dv;
            else if (c == 2) sa.z += dv;
            else             sa.w += dv;
        } else if (qq - 256 == tid) {
            if      (c == 0) sb.x += dv;
            else if (c == 1) sb.y += dv;
            else if (c == 2) sb.z += dv;
            else             sb.w += dv;
        }
        float4* orow = reinterpret_cast<float4*>(obase + (size_t)r * D);
        __stcs(orow + tid, sa);
        __stcs(orow + tid + 256, sb);
    }
}

extern "C" void kernel_launch(void* const* d_in, const int* in_sizes, int n_in,
                              void* d_out, int out_size) {
    const float* xt  = (const float*)d_in[0];
    const float* h   = (const float*)d_in[1];
    const float* Wa  = (const float*)d_in[2];
    const float* Wx  = (const float*)d_in[3];
    const float* ba  = (const float*)d_in[4];
    const float* bx  = (const float*)d_in[5];
    const float* Lam = (const float*)d_in[6];

    static bool attr_done = false;
    if (!attr_done) {
        cudaFuncSetAttribute(gates_kernel,
                             cudaFuncAttributeMaxDynamicSharedMemorySize,
                             SMEM_BYTES);
        attr_done = true;
    }

    gates_kernel<<<128, 512, SMEM_BYTES>>>(xt, h, Wa, Wx, ba, bx, Lam);

    dim3 grid(D / 16, B);
    writer_kernel<<<grid, 256>>>((float*)d_out);
}